// round 1
// baseline (speedup 1.0000x reference)
#include <cuda_runtime.h>

#define BSZ 4
#define TT  1024
#define DM  1024
#define HH  16
#define DK  64

// ---- device scratch (alloc-free rule: __device__ globals) ----
__device__ float g_qh[BSZ * TT * DM];              // (b, t, h, d)
__device__ float g_kh[BSZ * TT * DM];              // (b, h, t, d)
__device__ float g_vt[BSZ * TT * DM];              // (b, h, d, t)
__device__ float g_p[TT * DM];                     // (h, t, d)
__device__ float g_bd[67108864];                   // (b, h, t, s)  268MB
__device__ float g_concat[BSZ * TT * DM];          // (b, t, h*d)

// ======================================================================
// Generic NT GEMM:  C = A(MxK) @ B(NxK)^T (+bias), 128x128x8 tiles,
// 256 threads, 8x8 per-thread register tile. Output scattered by MODE.
// MODE 0: plain row-major (ldc = 1024)
// MODE 1: k-head layout  ((b*H+h)*T + s)*64 + d
// MODE 2: v-transposed   ((b*H+h)*64 + d)*T + s
// MODE 3: pos layout     ((h*T + m)*64 + d)
// ======================================================================
template <int MODE, bool BIAS>
__global__ __launch_bounds__(256) void gemm_nt(
    const float* __restrict__ A, const float* __restrict__ B,
    const float* __restrict__ bias, float* __restrict__ C, int K)
{
    __shared__ float As[8][132];
    __shared__ float Bs[8][132];
    int tid = threadIdx.x;
    int bm = blockIdx.y, bn = blockIdx.x;
    const float* Ag = A + (size_t)bm * 128 * K;
    const float* Bg = B + (size_t)bn * 128 * K;

    int lrow = tid >> 1;
    int lcol = (tid & 1) * 4;
    int tx = tid & 15, ty = tid >> 4;

    float acc[8][8];
#pragma unroll
    for (int i = 0; i < 8; i++)
#pragma unroll
        for (int j = 0; j < 8; j++) acc[i][j] = 0.0f;

    for (int k0 = 0; k0 < K; k0 += 8) {
        float4 av = *(const float4*)(Ag + (size_t)lrow * K + k0 + lcol);
        float4 bv = *(const float4*)(Bg + (size_t)lrow * K + k0 + lcol);
        As[lcol + 0][lrow] = av.x; As[lcol + 1][lrow] = av.y;
        As[lcol + 2][lrow] = av.z; As[lcol + 3][lrow] = av.w;
        Bs[lcol + 0][lrow] = bv.x; Bs[lcol + 1][lrow] = bv.y;
        Bs[lcol + 2][lrow] = bv.z; Bs[lcol + 3][lrow] = bv.w;
        __syncthreads();
#pragma unroll
        for (int kk = 0; kk < 8; kk++) {
            float4 a0 = *(const float4*)&As[kk][ty * 8];
            float4 a1 = *(const float4*)&As[kk][ty * 8 + 4];
            float4 b0 = *(const float4*)&Bs[kk][tx * 8];
            float4 b1 = *(const float4*)&Bs[kk][tx * 8 + 4];
            float a[8] = {a0.x, a0.y, a0.z, a0.w, a1.x, a1.y, a1.z, a1.w};
            float b[8] = {b0.x, b0.y, b0.z, b0.w, b1.x, b1.y, b1.z, b1.w};
#pragma unroll
            for (int i = 0; i < 8; i++)
#pragma unroll
                for (int j = 0; j < 8; j++) acc[i][j] += a[i] * b[j];
        }
        __syncthreads();
    }

    int row0 = bm * 128 + ty * 8;
    int col0 = bn * 128 + tx * 8;

    if (MODE == 2) {
#pragma unroll
        for (int j = 0; j < 8; j++) {
            int n = col0 + j;
            int h = n >> 6, d = n & 63;
            float bv = BIAS ? bias[n] : 0.0f;
#pragma unroll
            for (int iv = 0; iv < 2; iv++) {
                int m0 = row0 + iv * 4;
                int b = m0 >> 10, s = m0 & 1023;
                float4 o;
                o.x = acc[iv * 4 + 0][j] + bv;
                o.y = acc[iv * 4 + 1][j] + bv;
                o.z = acc[iv * 4 + 2][j] + bv;
                o.w = acc[iv * 4 + 3][j] + bv;
                size_t idx = (((size_t)(b * HH + h) * DK + d) * TT + s);
                *(float4*)(C + idx) = o;
            }
        }
    } else {
#pragma unroll
        for (int i = 0; i < 8; i++) {
            int m = row0 + i;
#pragma unroll
            for (int jv = 0; jv < 2; jv++) {
                int n = col0 + jv * 4;
                float4 o;
                o.x = acc[i][jv * 4 + 0] + (BIAS ? bias[n + 0] : 0.0f);
                o.y = acc[i][jv * 4 + 1] + (BIAS ? bias[n + 1] : 0.0f);
                o.z = acc[i][jv * 4 + 2] + (BIAS ? bias[n + 2] : 0.0f);
                o.w = acc[i][jv * 4 + 3] + (BIAS ? bias[n + 3] : 0.0f);
                size_t idx;
                if (MODE == 0) {
                    idx = (size_t)m * DM + n;
                } else if (MODE == 1) {
                    int b = m >> 10, s = m & 1023;
                    int h = n >> 6, d = n & 63;
                    idx = ((size_t)(b * HH + h) * TT + s) * DK + d;
                } else { // MODE == 3
                    int h = n >> 6, d = n & 63;
                    idx = ((size_t)h * TT + m) * DK + d;
                }
                *(float4*)(C + idx) = o;
            }
        }
    }
}

// ======================================================================
// Per-(b,h) GEMM with K=64: C(1024x1024) = (qh + posbias) @ B^T
// SCORES=false: B = g_p[h],  write raw BD to g_bd
// SCORES=true : B = g_kh[bh], add shifted-BD gather, mask, scale, write scores
// 128x128 tile, K split into two 32-wide smem passes. 256 threads, 8x8/thread.
// ======================================================================
template <bool SCORES>
__global__ __launch_bounds__(256) void attn_gemm(
    const int* __restrict__ mask, float* __restrict__ outp,
    const float* __restrict__ posb)
{
    __shared__ float As[32][132];
    __shared__ float Bs[32][132];
    int bh = blockIdx.z;
    int b = bh >> 4, h = bh & 15;
    const float* Ab = g_qh + ((size_t)b * TT * HH + h) * DK;   // row stride DM
    const float* Bb = SCORES ? (g_kh + (size_t)bh * TT * DK)
                             : (g_p + (size_t)h * TT * DK);
    const float* pb = posb + h * DK;
    int A0 = blockIdx.y * 128, N0 = blockIdx.x * 128;
    int tid = threadIdx.x;
    int tx = tid & 15, ty = tid >> 4;

    float acc[8][8];
#pragma unroll
    for (int i = 0; i < 8; i++)
#pragma unroll
        for (int j = 0; j < 8; j++) acc[i][j] = 0.0f;

#pragma unroll
    for (int k0 = 0; k0 < 64; k0 += 32) {
#pragma unroll
        for (int i = 0; i < 4; i++) {
            int fid = tid + i * 256;
            int m = fid >> 3;
            int k4 = (fid & 7) * 4;
            float4 av = *(const float4*)(Ab + (size_t)(A0 + m) * DM + k0 + k4);
            float4 pv = *(const float4*)(pb + k0 + k4);
            As[k4 + 0][m] = av.x + pv.x; As[k4 + 1][m] = av.y + pv.y;
            As[k4 + 2][m] = av.z + pv.z; As[k4 + 3][m] = av.w + pv.w;
            float4 bv = *(const float4*)(Bb + (size_t)(N0 + m) * DK + k0 + k4);
            Bs[k4 + 0][m] = bv.x; Bs[k4 + 1][m] = bv.y;
            Bs[k4 + 2][m] = bv.z; Bs[k4 + 3][m] = bv.w;
        }
        __syncthreads();
#pragma unroll 8
        for (int kk = 0; kk < 32; kk++) {
            float4 a0 = *(const float4*)&As[kk][ty * 8];
            float4 a1 = *(const float4*)&As[kk][ty * 8 + 4];
            float4 b0 = *(const float4*)&Bs[kk][tx * 8];
            float4 b1 = *(const float4*)&Bs[kk][tx * 8 + 4];
            float a[8] = {a0.x, a0.y, a0.z, a0.w, a1.x, a1.y, a1.z, a1.w};
            float bb[8] = {b0.x, b0.y, b0.z, b0.w, b1.x, b1.y, b1.z, b1.w};
#pragma unroll
            for (int i = 0; i < 8; i++)
#pragma unroll
                for (int j = 0; j < 8; j++) acc[i][j] += a[i] * bb[j];
        }
        __syncthreads();
    }

    int a0r = A0 + ty * 8, c0 = N0 + tx * 8;
    if (!SCORES) {
        float* out = g_bd + (size_t)bh * TT * TT;
#pragma unroll
        for (int i = 0; i < 8; i++) {
#pragma unroll
            for (int jv = 0; jv < 2; jv++) {
                float4 o;
                o.x = acc[i][jv * 4 + 0]; o.y = acc[i][jv * 4 + 1];
                o.z = acc[i][jv * 4 + 2]; o.w = acc[i][jv * 4 + 3];
                *(float4*)(out + (size_t)(a0r + i) * TT + c0 + jv * 4) = o;
            }
        }
    } else {
        const float* BD = g_bd + (size_t)bh * TT * TT;
        const int* mrow = mask + (size_t)b * TT * TT;
        float* out = outp + (size_t)bh * TT * TT;
#pragma unroll
        for (int i = 0; i < 8; i++) {
            int a = a0r + i;
#pragma unroll
            for (int j = 0; j < 8; j++) {
                int c = c0 + j;
                float bd;
                if (c <= a)          bd = BD[(size_t)a * TT + (TT - 1 + c - a)];
                else if (c == a + 1) bd = 0.0f;
                else                 bd = BD[(size_t)(a + 1) * TT + (c - a - 2)];
                float s = (acc[i][j] + bd) * 0.125f;
                if (mrow[(size_t)a * TT + c] == 0) s = -10000.0f;
                out[(size_t)a * TT + c] = s;
            }
        }
    }
}

// ======================================================================
// Row softmax in place: one block per row (1024 floats -> 4/thread).
// ======================================================================
__global__ __launch_bounds__(256) void softmax_rows(float* __restrict__ attn)
{
    size_t r = blockIdx.x;
    float* p = attn + r * TT;
    int tid = threadIdx.x;
    float4 v = ((const float4*)p)[tid];
    float m = fmaxf(fmaxf(v.x, v.y), fmaxf(v.z, v.w));
#pragma unroll
    for (int o = 16; o > 0; o >>= 1) m = fmaxf(m, __shfl_xor_sync(0xffffffffu, m, o));
    __shared__ float red[8];
    int wid = tid >> 5, lane = tid & 31;
    if (lane == 0) red[wid] = m;
    __syncthreads();
    float M = red[0];
#pragma unroll
    for (int i = 1; i < 8; i++) M = fmaxf(M, red[i]);
    v.x = __expf(v.x - M); v.y = __expf(v.y - M);
    v.z = __expf(v.z - M); v.w = __expf(v.w - M);
    float s = v.x + v.y + v.z + v.w;
#pragma unroll
    for (int o = 16; o > 0; o >>= 1) s += __shfl_xor_sync(0xffffffffu, s, o);
    __syncthreads();
    if (lane == 0) red[wid] = s;
    __syncthreads();
    float S = 0.0f;
#pragma unroll
    for (int i = 0; i < 8; i++) S += red[i];
    float inv = 1.0f / S;
    v.x *= inv; v.y *= inv; v.z *= inv; v.w *= inv;
    ((float4*)p)[tid] = v;
}

// ======================================================================
// PV: per (b,h)  O(1024x64) = attn(1024x1024) @ vt(64x1024)^T -> concat
// 128x64x16 tiles, 256 threads, 8x4 per thread.
// ======================================================================
__global__ __launch_bounds__(256) void gemm_pv(
    const float* __restrict__ attn, const float* __restrict__ vt,
    float* __restrict__ concat)
{
    __shared__ float As[16][132];
    __shared__ float Bs[16][68];
    int bh = blockIdx.z;
    int b = bh >> 4, h = bh & 15;
    const float* Ag = attn + (size_t)bh * TT * TT + (size_t)blockIdx.y * 128 * TT;
    const float* Bg = vt + (size_t)bh * DK * TT;
    int tid = threadIdx.x;
    int tx = tid & 15, ty = tid >> 4;

    float acc[8][4];
#pragma unroll
    for (int i = 0; i < 8; i++)
#pragma unroll
        for (int j = 0; j < 4; j++) acc[i][j] = 0.0f;

    for (int k0 = 0; k0 < TT; k0 += 16) {
#pragma unroll
        for (int i = 0; i < 2; i++) {
            int fid = tid + i * 256;
            int m = fid >> 2, k4 = (fid & 3) * 4;
            float4 av = *(const float4*)(Ag + (size_t)m * TT + k0 + k4);
            As[k4 + 0][m] = av.x; As[k4 + 1][m] = av.y;
            As[k4 + 2][m] = av.z; As[k4 + 3][m] = av.w;
        }
        {
            int m = tid >> 2, k4 = (tid & 3) * 4;
            if (m < 64) {
                float4 bv = *(const float4*)(Bg + (size_t)m * TT + k0 + k4);
                Bs[k4 + 0][m] = bv.x; Bs[k4 + 1][m] = bv.y;
                Bs[k4 + 2][m] = bv.z; Bs[k4 + 3][m] = bv.w;
            }
        }
        __syncthreads();
#pragma unroll
        for (int kk = 0; kk < 16; kk++) {
            float4 a0 = *(const float4*)&As[kk][ty * 8];
            float4 a1 = *(const float4*)&As[kk][ty * 8 + 4];
            float4 b0 = *(const float4*)&Bs[kk][tx * 4];
            float a[8] = {a0.x, a0.y, a0.z, a0.w, a1.x, a1.y, a1.z, a1.w};
            float bb[4] = {b0.x, b0.y, b0.z, b0.w};
#pragma unroll
            for (int i = 0; i < 8; i++)
#pragma unroll
                for (int j = 0; j < 4; j++) acc[i][j] += a[i] * bb[j];
        }
        __syncthreads();
    }

    int t0 = blockIdx.y * 128 + ty * 8;
    int d0 = tx * 4;
#pragma unroll
    for (int i = 0; i < 8; i++) {
        float4 o;
        o.x = acc[i][0]; o.y = acc[i][1]; o.z = acc[i][2]; o.w = acc[i][3];
        *(float4*)(concat + ((size_t)(b * TT + t0 + i)) * DM + h * DK + d0) = o;
    }
}

// ======================================================================
extern "C" void kernel_launch(void* const* d_in, const int* in_sizes, int n_in,
                              void* d_out, int out_size)
{
    const float* q    = (const float*)d_in[0];
    const float* k    = (const float*)d_in[1];
    const float* v    = (const float*)d_in[2];
    const float* pos  = (const float*)d_in[3];
    const int*   mask = (const int*)d_in[4];
    const float* Wq   = (const float*)d_in[5];
    const float* bq   = (const float*)d_in[6];
    const float* Wk   = (const float*)d_in[7];
    const float* bk   = (const float*)d_in[8];
    const float* Wv   = (const float*)d_in[9];
    const float* bv   = (const float*)d_in[10];
    const float* Wp   = (const float*)d_in[11];
    const float* pbu  = (const float*)d_in[12];
    const float* pbv  = (const float*)d_in[13];
    const float* Wo   = (const float*)d_in[14];
    const float* bo   = (const float*)d_in[15];

    float *qh, *kh, *vt, *pp, *cc;
    cudaGetSymbolAddress((void**)&qh, g_qh);
    cudaGetSymbolAddress((void**)&kh, g_kh);
    cudaGetSymbolAddress((void**)&vt, g_vt);
    cudaGetSymbolAddress((void**)&pp, g_p);
    cudaGetSymbolAddress((void**)&cc, g_concat);

    float* out  = (float*)d_out;
    float* attn = out + (size_t)BSZ * TT * DM;

    dim3 blk(256);
    // Projections
    gemm_nt<0, true><<<dim3(8, 32), blk>>>(q, Wq, bq, qh, DM);
    gemm_nt<1, true><<<dim3(8, 32), blk>>>(k, Wk, bk, kh, DM);
    gemm_nt<2, true><<<dim3(8, 32), blk>>>(v, Wv, bv, vt, DM);
    gemm_nt<3, false><<<dim3(8, 8), blk>>>(pos, Wp, nullptr, pp, DM);
    // BD = (qh + pos_bias_v) @ p^T   -> g_bd
    attn_gemm<false><<<dim3(8, 8, 64), blk>>>(nullptr, nullptr, pbv);
    // scores = ((qh + pos_bias_u) @ kh^T + shift(BD)) / 8, mask -> attn region
    attn_gemm<true><<<dim3(8, 8, 64), blk>>>(mask, attn, pbu);
    // softmax rows in place
    softmax_rows<<<dim3(BSZ * HH * TT), blk>>>(attn);
    // out_h = attn @ vh -> concat
    gemm_pv<<<dim3(1, 8, 64), blk>>>(attn, vt, cc);
    // output = concat @ Wo^T + bo
    gemm_nt<0, true><<<dim3(8, 32), blk>>>(cc, Wo, bo, out, DM);
}

// round 2
// speedup vs baseline: 1.9496x; 1.9496x over previous
#include <cuda_runtime.h>
#include <cstdint>

#define BSZ 4
#define TT  1024
#define DM  1024
#define HH  16
#define DK  64
#define KPAD 20

// ---- device scratch (alloc-free rule: __device__ globals) ----
__device__ float g_qh[BSZ * TT * DM];              // (b, t, h, d)
__device__ float g_kh[BSZ * TT * DM];              // (b, h, t, d)
__device__ float g_vt[BSZ * TT * DM];              // (b, h, d, t)
__device__ float g_p[TT * DM];                     // (h, t, d)
__device__ float g_bd[67108864];                   // (b, h, t, s)
__device__ float g_concat[BSZ * TT * DM];          // (b, t, h*d)

// ---------------------------------------------------------------
__device__ __forceinline__ float to_tf32(float x) {
    uint32_t u;
    asm("cvt.rna.tf32.f32 %0, %1;" : "=r"(u) : "f"(x));
    return __uint_as_float(u);
}

__device__ __forceinline__ void mma8(float4& d, const uint32_t a[4], const uint32_t b[2]) {
    asm volatile(
        "mma.sync.aligned.m16n8k8.row.col.f32.tf32.tf32.f32 "
        "{%0,%1,%2,%3}, {%4,%5,%6,%7}, {%8,%9}, {%0,%1,%2,%3};\n"
        : "+f"(d.x), "+f"(d.y), "+f"(d.z), "+f"(d.w)
        : "r"(a[0]), "r"(a[1]), "r"(a[2]), "r"(a[3]), "r"(b[0]), "r"(b[1]));
}

// ======================================================================
// Tensor-core NT GEMM:  C = A(MxK) @ B(NxK)^T (+bias)
// CTA tile 128x128, k-tile 16, 8 warps (4m x 2n), warp tile 32x64.
// MODE 0: row-major (ld 1024)      MODE 1: k-head ((b*H+h)*T+s)*64+d
// MODE 2: v-transposed ((b*H+h)*64+d)*T+s   MODE 3: pos (h*T+m)*64+d
// ======================================================================
template <int MODE, bool BIAS>
__global__ __launch_bounds__(256) void gemm_tc(
    const float* __restrict__ A, const float* __restrict__ B,
    const float* __restrict__ bias, float* __restrict__ C, int K)
{
    __shared__ __align__(16) float As[128 * KPAD];
    __shared__ __align__(16) float Bs[128 * KPAD];
    int tid = threadIdx.x;
    int M0 = blockIdx.y * 128, N0 = blockIdx.x * 128;
    int w = tid >> 5, lane = tid & 31;
    int wm = w & 3, wn = w >> 2;
    int r = tid >> 2, c4 = (tid & 3) * 4;

    float4 acc[2][8];
#pragma unroll
    for (int i = 0; i < 2; i++)
#pragma unroll
        for (int j = 0; j < 8; j++) acc[i][j] = make_float4(0.f, 0.f, 0.f, 0.f);

    const float* Ag  = A + (size_t)(M0 + r) * K + c4;
    const float* Ag2 = Ag + (size_t)64 * K;
    const float* Bg  = B + (size_t)(N0 + r) * K + c4;
    const float* Bg2 = Bg + (size_t)64 * K;

    for (int k0 = 0; k0 < K; k0 += 16) {
        float4 va  = *(const float4*)(Ag + k0);
        float4 va2 = *(const float4*)(Ag2 + k0);
        float4 vb  = *(const float4*)(Bg + k0);
        float4 vb2 = *(const float4*)(Bg2 + k0);
        *(float4*)&As[r * KPAD + c4] =
            make_float4(to_tf32(va.x), to_tf32(va.y), to_tf32(va.z), to_tf32(va.w));
        *(float4*)&As[(r + 64) * KPAD + c4] =
            make_float4(to_tf32(va2.x), to_tf32(va2.y), to_tf32(va2.z), to_tf32(va2.w));
        *(float4*)&Bs[r * KPAD + c4] =
            make_float4(to_tf32(vb.x), to_tf32(vb.y), to_tf32(vb.z), to_tf32(vb.w));
        *(float4*)&Bs[(r + 64) * KPAD + c4] =
            make_float4(to_tf32(vb2.x), to_tf32(vb2.y), to_tf32(vb2.z), to_tf32(vb2.w));
        __syncthreads();
#pragma unroll
        for (int ks = 0; ks < 16; ks += 8) {
            uint32_t bf[8][2];
#pragma unroll
            for (int nt = 0; nt < 8; nt++) {
                int nb = wn * 64 + nt * 8 + (lane >> 2);
                bf[nt][0] = __float_as_uint(Bs[nb * KPAD + ks + (lane & 3)]);
                bf[nt][1] = __float_as_uint(Bs[nb * KPAD + ks + (lane & 3) + 4]);
            }
#pragma unroll
            for (int mt = 0; mt < 2; mt++) {
                int mb = wm * 32 + mt * 16 + (lane >> 2);
                uint32_t af[4];
                af[0] = __float_as_uint(As[mb * KPAD + ks + (lane & 3)]);
                af[1] = __float_as_uint(As[(mb + 8) * KPAD + ks + (lane & 3)]);
                af[2] = __float_as_uint(As[mb * KPAD + ks + (lane & 3) + 4]);
                af[3] = __float_as_uint(As[(mb + 8) * KPAD + ks + (lane & 3) + 4]);
#pragma unroll
                for (int nt = 0; nt < 8; nt++) mma8(acc[mt][nt], af, bf[nt]);
            }
        }
        __syncthreads();
    }

    int lr = lane >> 2, lc2 = (lane & 3) * 2;
#pragma unroll
    for (int mt = 0; mt < 2; mt++) {
#pragma unroll
        for (int nt = 0; nt < 8; nt++) {
            int m = M0 + wm * 32 + mt * 16 + lr;
            int n = N0 + wn * 64 + nt * 8 + lc2;
            float b0 = BIAS ? bias[n] : 0.0f;
            float b1 = BIAS ? bias[n + 1] : 0.0f;
            float4 c = acc[mt][nt];
#pragma unroll
            for (int half = 0; half < 2; half++) {
                int mm = m + half * 8;
                float v0 = (half ? c.z : c.x) + b0;
                float v1 = (half ? c.w : c.y) + b1;
                if (MODE == 0) {
                    *(float2*)(C + (size_t)mm * DM + n) = make_float2(v0, v1);
                } else if (MODE == 1) {
                    int b = mm >> 10, s = mm & 1023;
                    int h = n >> 6, d = n & 63;
                    size_t idx = ((size_t)(b * HH + h) * TT + s) * DK + d;
                    *(float2*)(C + idx) = make_float2(v0, v1);
                } else if (MODE == 2) {
                    int b = mm >> 10, s = mm & 1023;
                    int h = n >> 6, d = n & 63;
                    size_t idx = ((size_t)(b * HH + h) * DK + d) * TT + s;
                    C[idx] = v0;
                    C[idx + TT] = v1;
                } else { // MODE 3
                    int h = n >> 6, d = n & 63;
                    size_t idx = ((size_t)h * TT + mm) * DK + d;
                    *(float2*)(C + idx) = make_float2(v0, v1);
                }
            }
        }
    }
}

// ======================================================================
// Per-(b,h) tensor-core GEMM, K=64:  C = (qh + posbias) @ B^T
// SCORES=false: B = g_p[h]  -> raw BD into g_bd
// SCORES=true : B = g_kh[bh], + shifted-BD gather + mask + 1/8 scale
// ======================================================================
template <bool SCORES>
__global__ __launch_bounds__(256) void attn_tc(
    const int* __restrict__ mask, float* __restrict__ outp,
    const float* __restrict__ posb)
{
    __shared__ __align__(16) float As[128 * KPAD];
    __shared__ __align__(16) float Bs[128 * KPAD];
    int bh = blockIdx.z;
    int b = bh >> 4, h = bh & 15;
    int tid = threadIdx.x;
    int M0 = blockIdx.y * 128, N0 = blockIdx.x * 128;
    int w = tid >> 5, lane = tid & 31;
    int wm = w & 3, wn = w >> 2;
    int r = tid >> 2, c4 = (tid & 3) * 4;

    const float* Ab = g_qh + (size_t)b * TT * DM + h * DK;          // row stride DM
    const float* Bb = SCORES ? (g_kh + (size_t)bh * TT * DK)
                             : (g_p + (size_t)h * TT * DK);         // row stride DK
    const float* pb = posb + h * DK;

    float4 acc[2][8];
#pragma unroll
    for (int i = 0; i < 2; i++)
#pragma unroll
        for (int j = 0; j < 8; j++) acc[i][j] = make_float4(0.f, 0.f, 0.f, 0.f);

#pragma unroll
    for (int k0 = 0; k0 < 64; k0 += 16) {
        float4 pv = *(const float4*)(pb + k0 + c4);
        float4 va  = *(const float4*)(Ab + (size_t)(M0 + r) * DM + k0 + c4);
        float4 va2 = *(const float4*)(Ab + (size_t)(M0 + r + 64) * DM + k0 + c4);
        float4 vb  = *(const float4*)(Bb + (size_t)(N0 + r) * DK + k0 + c4);
        float4 vb2 = *(const float4*)(Bb + (size_t)(N0 + r + 64) * DK + k0 + c4);
        *(float4*)&As[r * KPAD + c4] = make_float4(
            to_tf32(va.x + pv.x), to_tf32(va.y + pv.y),
            to_tf32(va.z + pv.z), to_tf32(va.w + pv.w));
        *(float4*)&As[(r + 64) * KPAD + c4] = make_float4(
            to_tf32(va2.x + pv.x), to_tf32(va2.y + pv.y),
            to_tf32(va2.z + pv.z), to_tf32(va2.w + pv.w));
        *(float4*)&Bs[r * KPAD + c4] =
            make_float4(to_tf32(vb.x), to_tf32(vb.y), to_tf32(vb.z), to_tf32(vb.w));
        *(float4*)&Bs[(r + 64) * KPAD + c4] =
            make_float4(to_tf32(vb2.x), to_tf32(vb2.y), to_tf32(vb2.z), to_tf32(vb2.w));
        __syncthreads();
#pragma unroll
        for (int ks = 0; ks < 16; ks += 8) {
            uint32_t bf[8][2];
#pragma unroll
            for (int nt = 0; nt < 8; nt++) {
                int nb = wn * 64 + nt * 8 + (lane >> 2);
                bf[nt][0] = __float_as_uint(Bs[nb * KPAD + ks + (lane & 3)]);
                bf[nt][1] = __float_as_uint(Bs[nb * KPAD + ks + (lane & 3) + 4]);
            }
#pragma unroll
            for (int mt = 0; mt < 2; mt++) {
                int mb = wm * 32 + mt * 16 + (lane >> 2);
                uint32_t af[4];
                af[0] = __float_as_uint(As[mb * KPAD + ks + (lane & 3)]);
                af[1] = __float_as_uint(As[(mb + 8) * KPAD + ks + (lane & 3)]);
                af[2] = __float_as_uint(As[mb * KPAD + ks + (lane & 3) + 4]);
                af[3] = __float_as_uint(As[(mb + 8) * KPAD + ks + (lane & 3) + 4]);
#pragma unroll
                for (int nt = 0; nt < 8; nt++) mma8(acc[mt][nt], af, bf[nt]);
            }
        }
        __syncthreads();
    }

    int lr = lane >> 2, lc2 = (lane & 3) * 2;
    if (!SCORES) {
        float* out = g_bd + (size_t)bh * TT * TT;
#pragma unroll
        for (int mt = 0; mt < 2; mt++)
#pragma unroll
            for (int nt = 0; nt < 8; nt++) {
                int m = M0 + wm * 32 + mt * 16 + lr;
                int n = N0 + wn * 64 + nt * 8 + lc2;
                float4 c = acc[mt][nt];
                *(float2*)(out + (size_t)m * TT + n) = make_float2(c.x, c.y);
                *(float2*)(out + (size_t)(m + 8) * TT + n) = make_float2(c.z, c.w);
            }
    } else {
        const float* BD = g_bd + (size_t)bh * TT * TT;
        const int* mk = mask + (size_t)b * TT * TT;
        float* out = outp + (size_t)bh * TT * TT;
#pragma unroll
        for (int mt = 0; mt < 2; mt++)
#pragma unroll
            for (int nt = 0; nt < 8; nt++) {
                int m = M0 + wm * 32 + mt * 16 + lr;
                int n = N0 + wn * 64 + nt * 8 + lc2;
                float4 c = acc[mt][nt];
                float vals[4] = {c.x, c.y, c.z, c.w};
#pragma unroll
                for (int e = 0; e < 4; e++) {
                    int a = m + (e >= 2 ? 8 : 0);
                    int cc = n + (e & 1);
                    float bd;
                    if (cc <= a)          bd = BD[(size_t)a * TT + (TT - 1 + cc - a)];
                    else if (cc == a + 1) bd = 0.0f;
                    else                  bd = BD[(size_t)(a + 1) * TT + (cc - a - 2)];
                    float s = (vals[e] + bd) * 0.125f;
                    if (mk[(size_t)a * TT + cc] == 0) s = -10000.0f;
                    out[(size_t)a * TT + cc] = s;
                }
            }
    }
}

// ======================================================================
// Row softmax in place
// ======================================================================
__global__ __launch_bounds__(256) void softmax_rows(float* __restrict__ attn)
{
    size_t rrow = blockIdx.x;
    float* p = attn + rrow * TT;
    int tid = threadIdx.x;
    float4 v = ((const float4*)p)[tid];
    float m = fmaxf(fmaxf(v.x, v.y), fmaxf(v.z, v.w));
#pragma unroll
    for (int o = 16; o > 0; o >>= 1) m = fmaxf(m, __shfl_xor_sync(0xffffffffu, m, o));
    __shared__ float red[8];
    int wid = tid >> 5, lane = tid & 31;
    if (lane == 0) red[wid] = m;
    __syncthreads();
    float M = red[0];
#pragma unroll
    for (int i = 1; i < 8; i++) M = fmaxf(M, red[i]);
    v.x = __expf(v.x - M); v.y = __expf(v.y - M);
    v.z = __expf(v.z - M); v.w = __expf(v.w - M);
    float s = v.x + v.y + v.z + v.w;
#pragma unroll
    for (int o = 16; o > 0; o >>= 1) s += __shfl_xor_sync(0xffffffffu, s, o);
    __syncthreads();
    if (lane == 0) red[wid] = s;
    __syncthreads();
    float S = 0.0f;
#pragma unroll
    for (int i = 0; i < 8; i++) S += red[i];
    float inv = 1.0f / S;
    v.x *= inv; v.y *= inv; v.z *= inv; v.w *= inv;
    ((float4*)p)[tid] = v;
}

// ======================================================================
// PV: per (b,h)  O(1024x64) = attn(1024x1024) @ vt(64x1024)^T -> concat
// CTA tile 128x64, 8 warps (4m x 2n), warp tile 32x32.
// ======================================================================
__global__ __launch_bounds__(256) void pv_tc(
    const float* __restrict__ attn, float* __restrict__ concat)
{
    __shared__ __align__(16) float As[128 * KPAD];
    __shared__ __align__(16) float Bs[64 * KPAD];
    int bh = blockIdx.z;
    int b = bh >> 4, h = bh & 15;
    int tid = threadIdx.x;
    int M0 = blockIdx.y * 128;
    int w = tid >> 5, lane = tid & 31;
    int wm = w & 3, wn = w >> 2;
    int r = tid >> 2, c4 = (tid & 3) * 4;

    const float* Ag = attn + (size_t)bh * TT * TT;
    const float* Bg = g_vt + (size_t)bh * DK * TT;

    float4 acc[2][4];
#pragma unroll
    for (int i = 0; i < 2; i++)
#pragma unroll
        for (int j = 0; j < 4; j++) acc[i][j] = make_float4(0.f, 0.f, 0.f, 0.f);

    for (int k0 = 0; k0 < TT; k0 += 16) {
        float4 va  = *(const float4*)(Ag + (size_t)(M0 + r) * TT + k0 + c4);
        float4 va2 = *(const float4*)(Ag + (size_t)(M0 + r + 64) * TT + k0 + c4);
        float4 vb  = *(const float4*)(Bg + (size_t)r * TT + k0 + c4);
        *(float4*)&As[r * KPAD + c4] =
            make_float4(to_tf32(va.x), to_tf32(va.y), to_tf32(va.z), to_tf32(va.w));
        *(float4*)&As[(r + 64) * KPAD + c4] =
            make_float4(to_tf32(va2.x), to_tf32(va2.y), to_tf32(va2.z), to_tf32(va2.w));
        *(float4*)&Bs[r * KPAD + c4] =
            make_float4(to_tf32(vb.x), to_tf32(vb.y), to_tf32(vb.z), to_tf32(vb.w));
        __syncthreads();
#pragma unroll
        for (int ks = 0; ks < 16; ks += 8) {
            uint32_t bf[4][2];
#pragma unroll
            for (int nt = 0; nt < 4; nt++) {
                int nb = wn * 32 + nt * 8 + (lane >> 2);
                bf[nt][0] = __float_as_uint(Bs[nb * KPAD + ks + (lane & 3)]);
                bf[nt][1] = __float_as_uint(Bs[nb * KPAD + ks + (lane & 3) + 4]);
            }
#pragma unroll
            for (int mt = 0; mt < 2; mt++) {
                int mb = wm * 32 + mt * 16 + (lane >> 2);
                uint32_t af[4];
                af[0] = __float_as_uint(As[mb * KPAD + ks + (lane & 3)]);
                af[1] = __float_as_uint(As[(mb + 8) * KPAD + ks + (lane & 3)]);
                af[2] = __float_as_uint(As[mb * KPAD + ks + (lane & 3) + 4]);
                af[3] = __float_as_uint(As[(mb + 8) * KPAD + ks + (lane & 3) + 4]);
#pragma unroll
                for (int nt = 0; nt < 4; nt++) mma8(acc[mt][nt], af, bf[nt]);
            }
        }
        __syncthreads();
    }

    int lr = lane >> 2, lc2 = (lane & 3) * 2;
#pragma unroll
    for (int mt = 0; mt < 2; mt++)
#pragma unroll
        for (int nt = 0; nt < 4; nt++) {
            int t = M0 + wm * 32 + mt * 16 + lr;
            int d = wn * 32 + nt * 8 + lc2;
            float4 c = acc[mt][nt];
            *(float2*)(concat + ((size_t)(b * TT + t)) * DM + h * DK + d) =
                make_float2(c.x, c.y);
            *(float2*)(concat + ((size_t)(b * TT + t + 8)) * DM + h * DK + d) =
                make_float2(c.z, c.w);
        }
}

// ======================================================================
extern "C" void kernel_launch(void* const* d_in, const int* in_sizes, int n_in,
                              void* d_out, int out_size)
{
    const float* q    = (const float*)d_in[0];
    const float* k    = (const float*)d_in[1];
    const float* v    = (const float*)d_in[2];
    const float* pos  = (const float*)d_in[3];
    const int*   mask = (const int*)d_in[4];
    const float* Wq   = (const float*)d_in[5];
    const float* bq   = (const float*)d_in[6];
    const float* Wk   = (const float*)d_in[7];
    const float* bk   = (const float*)d_in[8];
    const float* Wv   = (const float*)d_in[9];
    const float* bv   = (const float*)d_in[10];
    const float* Wp   = (const float*)d_in[11];
    const float* pbu  = (const float*)d_in[12];
    const float* pbv  = (const float*)d_in[13];
    const float* Wo   = (const float*)d_in[14];
    const float* bo   = (const float*)d_in[15];

    float *qh, *cc;
    cudaGetSymbolAddress((void**)&qh, g_qh);
    cudaGetSymbolAddress((void**)&cc, g_concat);
    float *kh, *vt, *pp;
    cudaGetSymbolAddress((void**)&kh, g_kh);
    cudaGetSymbolAddress((void**)&vt, g_vt);
    cudaGetSymbolAddress((void**)&pp, g_p);

    float* out  = (float*)d_out;
    float* attn = out + (size_t)BSZ * TT * DM;

    dim3 blk(256);
    // Projections (tensor core tf32)
    gemm_tc<0, true><<<dim3(8, 32), blk>>>(q, Wq, bq, qh, DM);   // qh (b,t,h*d) row-major
    gemm_tc<1, true><<<dim3(8, 32), blk>>>(k, Wk, bk, kh, DM);
    gemm_tc<2, true><<<dim3(8, 32), blk>>>(v, Wv, bv, vt, DM);
    gemm_tc<3, false><<<dim3(8, 8), blk>>>(pos, Wp, nullptr, pp, DM);
    // BD = (qh + pos_bias_v) @ p^T -> g_bd
    attn_tc<false><<<dim3(8, 8, 64), blk>>>(nullptr, nullptr, pbv);
    // scores = ((qh + pos_bias_u) @ kh^T + shift(BD)) / 8 + mask -> attn region
    attn_tc<true><<<dim3(8, 8, 64), blk>>>(mask, attn, pbu);
    // softmax rows in place
    softmax_rows<<<dim3(BSZ * HH * TT), blk>>>(attn);
    // out_h = attn @ vh -> concat
    pv_tc<<<dim3(1, 8, 64), blk>>>(attn, cc);
    // output = concat @ Wo^T + bo
    gemm_tc<0, true><<<dim3(8, 32), blk>>>(cc, Wo, bo, out, DM);
}

// round 3
// speedup vs baseline: 2.1431x; 1.0993x over previous
#include <cuda_runtime.h>
#include <cstdint>

#define BSZ 4
#define TT  1024
#define DM  1024
#define HH  16
#define DK  64
#define KPAD 20
#define STG (128 * KPAD)

// ---- device scratch (alloc-free rule: __device__ globals) ----
__device__ float g_qh[BSZ * TT * DM];              // (b, t, h, d)
__device__ float g_kh[BSZ * TT * DM];              // (b, h, t, d)
__device__ float g_vt[BSZ * TT * DM];              // (b, h, d, t)
__device__ float g_p[TT * DM];                     // (h, t, d)
__device__ float g_bd[67108864];                   // (b, h, t, s)
__device__ float g_concat[BSZ * TT * DM];          // (b, t, h*d)

// ---------------------------------------------------------------
__device__ __forceinline__ float to_tf32(float x) {
    uint32_t u;
    asm("cvt.rna.tf32.f32 %0, %1;" : "=r"(u) : "f"(x));
    return __uint_as_float(u);
}
__device__ __forceinline__ uint32_t tf32u(float x) {
    uint32_t u;
    asm("cvt.rna.tf32.f32 %0, %1;" : "=r"(u) : "f"(x));
    return u;
}

__device__ __forceinline__ void mma8(float4& d, const uint32_t a[4], const uint32_t b[2]) {
    asm volatile(
        "mma.sync.aligned.m16n8k8.row.col.f32.tf32.tf32.f32 "
        "{%0,%1,%2,%3}, {%4,%5,%6,%7}, {%8,%9}, {%0,%1,%2,%3};\n"
        : "+f"(d.x), "+f"(d.y), "+f"(d.z), "+f"(d.w)
        : "r"(a[0]), "r"(a[1]), "r"(a[2]), "r"(a[3]), "r"(b[0]), "r"(b[1]));
}

__device__ __forceinline__ void cpa16(uint32_t saddr, const float* g) {
    asm volatile("cp.async.ca.shared.global [%0], [%1], 16;\n" :: "r"(saddr), "l"(g));
}
__device__ __forceinline__ void cp_commit() {
    asm volatile("cp.async.commit_group;\n");
}
template <int N>
__device__ __forceinline__ void cp_wait() {
    asm volatile("cp.async.wait_group %0;\n" :: "n"(N));
}

struct QKVArgs {
    const float* A[3];
    const float* B[3];
    const float* bias[3];
    float* C[3];
};

// ======================================================================
// Pipelined tensor-core NT GEMM: C = A(MxK) @ B(NxK)^T (+bias)
// CTA 128x128, k-tile 16, double-buffered cp.async, 8 warps (4m x 2n).
// mode_sel >= 0 -> that mode for all blocks; mode_sel < 0 -> mode = blockIdx.z
// MODE 0: row-major   MODE 1: k-head ((b*H+h)*T+s)*64+d
// MODE 2: v-transposed ((b*H+h)*64+d)*T+s   MODE 3: pos (h*T+m)*64+d
// ======================================================================
__global__ __launch_bounds__(256) void gemm_pipe(QKVArgs args, int K, int mode_sel)
{
    __shared__ __align__(16) float As[2 * STG];
    __shared__ __align__(16) float Bs[2 * STG];
    int z = blockIdx.z;
    int mode = (mode_sel >= 0) ? mode_sel : z;
    const float* A = args.A[z];
    const float* B = args.B[z];
    const float* bias = args.bias[z];
    float* C = args.C[z];
    bool has_bias = (bias != nullptr);

    int tid = threadIdx.x;
    int M0 = blockIdx.y * 128, N0 = blockIdx.x * 128;
    int w = tid >> 5, lane = tid & 31;
    int wm = w & 3, wn = w >> 2;
    int r = tid >> 2, c4 = (tid & 3) * 4;

    float4 acc[2][8];
#pragma unroll
    for (int i = 0; i < 2; i++)
#pragma unroll
        for (int j = 0; j < 8; j++) acc[i][j] = make_float4(0.f, 0.f, 0.f, 0.f);

    const float* Ag = A + (size_t)(M0 + r) * K + c4;
    const float* Bg = B + (size_t)(N0 + r) * K + c4;
    uint32_t sA = (uint32_t)__cvta_generic_to_shared(As);
    uint32_t sB = (uint32_t)__cvta_generic_to_shared(Bs);
    uint32_t offA0 = (r * KPAD + c4) * 4;
    uint32_t offA1 = ((r + 64) * KPAD + c4) * 4;

    // prologue: stage 0
    cpa16(sA + offA0, Ag);
    cpa16(sA + offA1, Ag + (size_t)64 * K);
    cpa16(sB + offA0, Bg);
    cpa16(sB + offA1, Bg + (size_t)64 * K);
    cp_commit();

    int KT = K >> 4;
    for (int kt = 0; kt < KT; kt++) {
        if (kt + 1 < KT) {
            int st = (kt + 1) & 1;
            int k0 = (kt + 1) << 4;
            cpa16(sA + st * STG * 4 + offA0, Ag + k0);
            cpa16(sA + st * STG * 4 + offA1, Ag + (size_t)64 * K + k0);
            cpa16(sB + st * STG * 4 + offA0, Bg + k0);
            cpa16(sB + st * STG * 4 + offA1, Bg + (size_t)64 * K + k0);
            cp_commit();
            cp_wait<1>();
        } else {
            cp_wait<0>();
        }
        __syncthreads();
        const float* as = As + (kt & 1) * STG;
        const float* bs = Bs + (kt & 1) * STG;
#pragma unroll
        for (int ks = 0; ks < 16; ks += 8) {
            uint32_t bf[8][2];
#pragma unroll
            for (int nt = 0; nt < 8; nt++) {
                int nb = wn * 64 + nt * 8 + (lane >> 2);
                bf[nt][0] = tf32u(bs[nb * KPAD + ks + (lane & 3)]);
                bf[nt][1] = tf32u(bs[nb * KPAD + ks + (lane & 3) + 4]);
            }
#pragma unroll
            for (int mt = 0; mt < 2; mt++) {
                int mb = wm * 32 + mt * 16 + (lane >> 2);
                uint32_t af[4];
                af[0] = tf32u(as[mb * KPAD + ks + (lane & 3)]);
                af[1] = tf32u(as[(mb + 8) * KPAD + ks + (lane & 3)]);
                af[2] = tf32u(as[mb * KPAD + ks + (lane & 3) + 4]);
                af[3] = tf32u(as[(mb + 8) * KPAD + ks + (lane & 3) + 4]);
#pragma unroll
                for (int nt = 0; nt < 8; nt++) mma8(acc[mt][nt], af, bf[nt]);
            }
        }
        __syncthreads();
    }

    int lr = lane >> 2, lc2 = (lane & 3) * 2;
#pragma unroll
    for (int mt = 0; mt < 2; mt++) {
#pragma unroll
        for (int nt = 0; nt < 8; nt++) {
            int m = M0 + wm * 32 + mt * 16 + lr;
            int n = N0 + wn * 64 + nt * 8 + lc2;
            float b0 = has_bias ? bias[n] : 0.0f;
            float b1 = has_bias ? bias[n + 1] : 0.0f;
            float4 c = acc[mt][nt];
#pragma unroll
            for (int half = 0; half < 2; half++) {
                int mm = m + half * 8;
                float v0 = (half ? c.z : c.x) + b0;
                float v1 = (half ? c.w : c.y) + b1;
                if (mode == 0) {
                    *(float2*)(C + (size_t)mm * DM + n) = make_float2(v0, v1);
                } else if (mode == 1) {
                    int b = mm >> 10, s = mm & 1023;
                    int h = n >> 6, d = n & 63;
                    size_t idx = ((size_t)(b * HH + h) * TT + s) * DK + d;
                    *(float2*)(C + idx) = make_float2(v0, v1);
                } else if (mode == 2) {
                    int b = mm >> 10, s = mm & 1023;
                    int h = n >> 6, d = n & 63;
                    size_t idx = ((size_t)(b * HH + h) * DK + d) * TT + s;
                    C[idx] = v0;
                    C[idx + TT] = v1;
                } else { // mode 3
                    int h = n >> 6, d = n & 63;
                    size_t idx = ((size_t)h * TT + mm) * DK + d;
                    *(float2*)(C + idx) = make_float2(v0, v1);
                }
            }
        }
    }
}

// ======================================================================
// Per-(b,h) tensor-core GEMM, K=64:  C = (qh + posbias) @ B^T
// SCORES=false: B = g_p[h]  -> raw BD into g_bd
// SCORES=true : B = g_kh[bh], + shifted-BD gather + mask + 1/8 scale
// ======================================================================
template <bool SCORES>
__global__ __launch_bounds__(256) void attn_tc(
    const int* __restrict__ mask, float* __restrict__ outp,
    const float* __restrict__ posb)
{
    __shared__ __align__(16) float As[128 * KPAD];
    __shared__ __align__(16) float Bs[128 * KPAD];
    int bh = blockIdx.z;
    int b = bh >> 4, h = bh & 15;
    int tid = threadIdx.x;
    int M0 = blockIdx.y * 128, N0 = blockIdx.x * 128;
    int w = tid >> 5, lane = tid & 31;
    int wm = w & 3, wn = w >> 2;
    int r = tid >> 2, c4 = (tid & 3) * 4;

    const float* Ab = g_qh + (size_t)b * TT * DM + h * DK;
    const float* Bb = SCORES ? (g_kh + (size_t)bh * TT * DK)
                             : (g_p + (size_t)h * TT * DK);
    const float* pb = posb + h * DK;

    float4 acc[2][8];
#pragma unroll
    for (int i = 0; i < 2; i++)
#pragma unroll
        for (int j = 0; j < 8; j++) acc[i][j] = make_float4(0.f, 0.f, 0.f, 0.f);

#pragma unroll
    for (int k0 = 0; k0 < 64; k0 += 16) {
        float4 pv = *(const float4*)(pb + k0 + c4);
        float4 va  = *(const float4*)(Ab + (size_t)(M0 + r) * DM + k0 + c4);
        float4 va2 = *(const float4*)(Ab + (size_t)(M0 + r + 64) * DM + k0 + c4);
        float4 vb  = *(const float4*)(Bb + (size_t)(N0 + r) * DK + k0 + c4);
        float4 vb2 = *(const float4*)(Bb + (size_t)(N0 + r + 64) * DK + k0 + c4);
        *(float4*)&As[r * KPAD + c4] = make_float4(
            to_tf32(va.x + pv.x), to_tf32(va.y + pv.y),
            to_tf32(va.z + pv.z), to_tf32(va.w + pv.w));
        *(float4*)&As[(r + 64) * KPAD + c4] = make_float4(
            to_tf32(va2.x + pv.x), to_tf32(va2.y + pv.y),
            to_tf32(va2.z + pv.z), to_tf32(va2.w + pv.w));
        *(float4*)&Bs[r * KPAD + c4] =
            make_float4(to_tf32(vb.x), to_tf32(vb.y), to_tf32(vb.z), to_tf32(vb.w));
        *(float4*)&Bs[(r + 64) * KPAD + c4] =
            make_float4(to_tf32(vb2.x), to_tf32(vb2.y), to_tf32(vb2.z), to_tf32(vb2.w));
        __syncthreads();
#pragma unroll
        for (int ks = 0; ks < 16; ks += 8) {
            uint32_t bf[8][2];
#pragma unroll
            for (int nt = 0; nt < 8; nt++) {
                int nb = wn * 64 + nt * 8 + (lane >> 2);
                bf[nt][0] = __float_as_uint(Bs[nb * KPAD + ks + (lane & 3)]);
                bf[nt][1] = __float_as_uint(Bs[nb * KPAD + ks + (lane & 3) + 4]);
            }
#pragma unroll
            for (int mt = 0; mt < 2; mt++) {
                int mb = wm * 32 + mt * 16 + (lane >> 2);
                uint32_t af[4];
                af[0] = __float_as_uint(As[mb * KPAD + ks + (lane & 3)]);
                af[1] = __float_as_uint(As[(mb + 8) * KPAD + ks + (lane & 3)]);
                af[2] = __float_as_uint(As[mb * KPAD + ks + (lane & 3) + 4]);
                af[3] = __float_as_uint(As[(mb + 8) * KPAD + ks + (lane & 3) + 4]);
#pragma unroll
                for (int nt = 0; nt < 8; nt++) mma8(acc[mt][nt], af, bf[nt]);
            }
        }
        __syncthreads();
    }

    int lr = lane >> 2, lc2 = (lane & 3) * 2;
    if (!SCORES) {
        float* out = g_bd + (size_t)bh * TT * TT;
#pragma unroll
        for (int mt = 0; mt < 2; mt++)
#pragma unroll
            for (int nt = 0; nt < 8; nt++) {
                int m = M0 + wm * 32 + mt * 16 + lr;
                int n = N0 + wn * 64 + nt * 8 + lc2;
                float4 c = acc[mt][nt];
                *(float2*)(out + (size_t)m * TT + n) = make_float2(c.x, c.y);
                *(float2*)(out + (size_t)(m + 8) * TT + n) = make_float2(c.z, c.w);
            }
    } else {
        const float* BD = g_bd + (size_t)bh * TT * TT;
        const int* mk = mask + (size_t)b * TT * TT;
        float* out = outp + (size_t)bh * TT * TT;
#pragma unroll
        for (int mt = 0; mt < 2; mt++)
#pragma unroll
            for (int nt = 0; nt < 8; nt++) {
                int m = M0 + wm * 32 + mt * 16 + lr;
                int n = N0 + wn * 64 + nt * 8 + lc2;
                float4 c = acc[mt][nt];
                float vals[4] = {c.x, c.y, c.z, c.w};
#pragma unroll
                for (int e = 0; e < 4; e++) {
                    int a = m + (e >= 2 ? 8 : 0);
                    int cc = n + (e & 1);
                    float bd;
                    if (cc <= a)          bd = BD[(size_t)a * TT + (TT - 1 + cc - a)];
                    else if (cc == a + 1) bd = 0.0f;
                    else                  bd = BD[(size_t)(a + 1) * TT + (cc - a - 2)];
                    float s = (vals[e] + bd) * 0.125f;
                    if (mk[(size_t)a * TT + cc] == 0) s = -10000.0f;
                    out[(size_t)a * TT + cc] = s;
                }
            }
    }
}

// ======================================================================
// Row softmax in place
// ======================================================================
__global__ __launch_bounds__(256) void softmax_rows(float* __restrict__ attn)
{
    size_t rrow = blockIdx.x;
    float* p = attn + rrow * TT;
    int tid = threadIdx.x;
    float4 v = ((const float4*)p)[tid];
    float m = fmaxf(fmaxf(v.x, v.y), fmaxf(v.z, v.w));
#pragma unroll
    for (int o = 16; o > 0; o >>= 1) m = fmaxf(m, __shfl_xor_sync(0xffffffffu, m, o));
    __shared__ float red[8];
    int wid = tid >> 5, lane = tid & 31;
    if (lane == 0) red[wid] = m;
    __syncthreads();
    float M = red[0];
#pragma unroll
    for (int i = 1; i < 8; i++) M = fmaxf(M, red[i]);
    v.x = __expf(v.x - M); v.y = __expf(v.y - M);
    v.z = __expf(v.z - M); v.w = __expf(v.w - M);
    float s = v.x + v.y + v.z + v.w;
#pragma unroll
    for (int o = 16; o > 0; o >>= 1) s += __shfl_xor_sync(0xffffffffu, s, o);
    __syncthreads();
    if (lane == 0) red[wid] = s;
    __syncthreads();
    float S = 0.0f;
#pragma unroll
    for (int i = 0; i < 8; i++) S += red[i];
    float inv = 1.0f / S;
    v.x *= inv; v.y *= inv; v.z *= inv; v.w *= inv;
    ((float4*)p)[tid] = v;
}

// ======================================================================
// PV (pipelined): per (b,h)  O(1024x64) = attn @ vt^T -> concat
// CTA 128x64, 8 warps (4m x 2n), warp tile 32x32, cp.async double buffer.
// ======================================================================
__global__ __launch_bounds__(256) void pv_pipe(
    const float* __restrict__ attn, float* __restrict__ concat)
{
    __shared__ __align__(16) float As[2 * STG];
    __shared__ __align__(16) float Bs[2 * 64 * KPAD];
    int bh = blockIdx.z;
    int b = bh >> 4, h = bh & 15;
    int tid = threadIdx.x;
    int M0 = blockIdx.y * 128;
    int w = tid >> 5, lane = tid & 31;
    int wm = w & 3, wn = w >> 2;
    int r = tid >> 2, c4 = (tid & 3) * 4;

    const float* Ag = attn + (size_t)bh * TT * TT + (size_t)(M0 + r) * TT + c4;
    const float* Bg = g_vt + (size_t)bh * DK * TT + (size_t)r * TT + c4;
    uint32_t sA = (uint32_t)__cvta_generic_to_shared(As);
    uint32_t sB = (uint32_t)__cvta_generic_to_shared(Bs);
    uint32_t offA0 = (r * KPAD + c4) * 4;
    uint32_t offA1 = ((r + 64) * KPAD + c4) * 4;

    float4 acc[2][4];
#pragma unroll
    for (int i = 0; i < 2; i++)
#pragma unroll
        for (int j = 0; j < 4; j++) acc[i][j] = make_float4(0.f, 0.f, 0.f, 0.f);

    cpa16(sA + offA0, Ag);
    cpa16(sA + offA1, Ag + (size_t)64 * TT);
    cpa16(sB + offA0, Bg);
    cp_commit();

    const int KT = TT >> 4;
    for (int kt = 0; kt < KT; kt++) {
        if (kt + 1 < KT) {
            int st = (kt + 1) & 1;
            int k0 = (kt + 1) << 4;
            cpa16(sA + st * STG * 4 + offA0, Ag + k0);
            cpa16(sA + st * STG * 4 + offA1, Ag + (size_t)64 * TT + k0);
            cpa16(sB + st * 64 * KPAD * 4 + offA0, Bg + k0);
            cp_commit();
            cp_wait<1>();
        } else {
            cp_wait<0>();
        }
        __syncthreads();
        const float* as = As + (kt & 1) * STG;
        const float* bs = Bs + (kt & 1) * 64 * KPAD;
#pragma unroll
        for (int ks = 0; ks < 16; ks += 8) {
            uint32_t bf[4][2];
#pragma unroll
            for (int nt = 0; nt < 4; nt++) {
                int nb = wn * 32 + nt * 8 + (lane >> 2);
                bf[nt][0] = tf32u(bs[nb * KPAD + ks + (lane & 3)]);
                bf[nt][1] = tf32u(bs[nb * KPAD + ks + (lane & 3) + 4]);
            }
#pragma unroll
            for (int mt = 0; mt < 2; mt++) {
                int mb = wm * 32 + mt * 16 + (lane >> 2);
                uint32_t af[4];
                af[0] = tf32u(as[mb * KPAD + ks + (lane & 3)]);
                af[1] = tf32u(as[(mb + 8) * KPAD + ks + (lane & 3)]);
                af[2] = tf32u(as[mb * KPAD + ks + (lane & 3) + 4]);
                af[3] = tf32u(as[(mb + 8) * KPAD + ks + (lane & 3) + 4]);
#pragma unroll
                for (int nt = 0; nt < 4; nt++) mma8(acc[mt][nt], af, bf[nt]);
            }
        }
        __syncthreads();
    }

    int lr = lane >> 2, lc2 = (lane & 3) * 2;
#pragma unroll
    for (int mt = 0; mt < 2; mt++)
#pragma unroll
        for (int nt = 0; nt < 4; nt++) {
            int t = M0 + wm * 32 + mt * 16 + lr;
            int d = wn * 32 + nt * 8 + lc2;
            float4 c = acc[mt][nt];
            *(float2*)(concat + ((size_t)(b * TT + t)) * DM + h * DK + d) =
                make_float2(c.x, c.y);
            *(float2*)(concat + ((size_t)(b * TT + t + 8)) * DM + h * DK + d) =
                make_float2(c.z, c.w);
        }
}

// ======================================================================
extern "C" void kernel_launch(void* const* d_in, const int* in_sizes, int n_in,
                              void* d_out, int out_size)
{
    const float* q    = (const float*)d_in[0];
    const float* k    = (const float*)d_in[1];
    const float* v    = (const float*)d_in[2];
    const float* pos  = (const float*)d_in[3];
    const int*   mask = (const int*)d_in[4];
    const float* Wq   = (const float*)d_in[5];
    const float* bq   = (const float*)d_in[6];
    const float* Wk   = (const float*)d_in[7];
    const float* bk   = (const float*)d_in[8];
    const float* Wv   = (const float*)d_in[9];
    const float* bv   = (const float*)d_in[10];
    const float* Wp   = (const float*)d_in[11];
    const float* pbu  = (const float*)d_in[12];
    const float* pbv  = (const float*)d_in[13];
    const float* Wo   = (const float*)d_in[14];
    const float* bo   = (const float*)d_in[15];

    float *qh, *kh, *vt, *pp, *cc;
    cudaGetSymbolAddress((void**)&qh, g_qh);
    cudaGetSymbolAddress((void**)&kh, g_kh);
    cudaGetSymbolAddress((void**)&vt, g_vt);
    cudaGetSymbolAddress((void**)&pp, g_p);
    cudaGetSymbolAddress((void**)&cc, g_concat);

    float* out  = (float*)d_out;
    float* attn = out + (size_t)BSZ * TT * DM;

    dim3 blk(256);

    // Q, K, V projections batched in one launch (z -> mode 0/1/2)
    QKVArgs qa;
    qa.A[0] = q;  qa.A[1] = k;  qa.A[2] = v;
    qa.B[0] = Wq; qa.B[1] = Wk; qa.B[2] = Wv;
    qa.bias[0] = bq; qa.bias[1] = bk; qa.bias[2] = bv;
    qa.C[0] = qh; qa.C[1] = kh; qa.C[2] = vt;
    gemm_pipe<<<dim3(8, 32, 3), blk>>>(qa, DM, -1);

    // pos projection (mode 3)
    QKVArgs pa = {};
    pa.A[0] = pos; pa.B[0] = Wp; pa.bias[0] = nullptr; pa.C[0] = pp;
    gemm_pipe<<<dim3(8, 8, 1), blk>>>(pa, DM, 3);

    // BD = (qh + pos_bias_v) @ p^T -> g_bd
    attn_tc<false><<<dim3(8, 8, 64), blk>>>(nullptr, nullptr, pbv);
    // scores = ((qh + pos_bias_u) @ kh^T + shift(BD)) / 8 + mask -> attn region
    attn_tc<true><<<dim3(8, 8, 64), blk>>>(mask, attn, pbu);
    // softmax rows in place
    softmax_rows<<<dim3(BSZ * HH * TT), blk>>>(attn);
    // out_h = attn @ vh -> concat
    pv_pipe<<<dim3(1, 8, 64), blk>>>(attn, cc);

    // output = concat @ Wo^T + bo (mode 0)
    QKVArgs oa = {};
    oa.A[0] = cc; oa.B[0] = Wo; oa.bias[0] = bo; oa.C[0] = out;
    gemm_pipe<<<dim3(8, 32, 1), blk>>>(oa, DM, 0);
}